// round 15
// baseline (speedup 1.0000x reference)
#include <cuda_runtime.h>
#include <cuda_bf16.h>
#include <math.h>
#include <stdint.h>

#define B_  4
#define T_  4096
#define NE_ 2048
#define HD_ 128
#define M_TOT (B_ * T_)

// ---------------------------------------------------------------------------
// Device scratch (no allocations allowed)
// ---------------------------------------------------------------------------
__device__ __nv_bfloat16 g_wt_hi[3 * HD_ * NE_];
__device__ __nv_bfloat16 g_wt_lo[3 * HD_ * NE_];
__device__ __nv_bfloat16 g_Qhi[M_TOT * HD_], g_Qlo[M_TOT * HD_];
__device__ __nv_bfloat16 g_Khi[M_TOT * HD_], g_Klo[M_TOT * HD_];
__device__ __nv_bfloat16 g_Vthi[M_TOT * HD_], g_Vtlo[M_TOT * HD_];

// ---------------------------------------------------------------------------
// helpers
// ---------------------------------------------------------------------------
__device__ __forceinline__ void hmma16816(float* c, const uint32_t* a,
                                          uint32_t b0, uint32_t b1)
{
    asm volatile(
        "mma.sync.aligned.m16n8k16.row.col.f32.bf16.bf16.f32 "
        "{%0,%1,%2,%3}, {%4,%5,%6,%7}, {%8,%9}, {%0,%1,%2,%3};"
        : "+f"(c[0]), "+f"(c[1]), "+f"(c[2]), "+f"(c[3])
        : "r"(a[0]), "r"(a[1]), "r"(a[2]), "r"(a[3]), "r"(b0), "r"(b1));
}

__device__ __forceinline__ void ldsm_x4(uint32_t& r0, uint32_t& r1,
                                        uint32_t& r2, uint32_t& r3, uint32_t addr)
{
    asm volatile("ldmatrix.sync.aligned.m8n8.x4.shared.b16 {%0,%1,%2,%3}, [%4];"
                 : "=r"(r0), "=r"(r1), "=r"(r2), "=r"(r3) : "r"(addr));
}

__device__ __forceinline__ uint32_t smem_u32(const void* p) {
    uint32_t a;
    asm("{ .reg .u64 t; cvta.to.shared.u64 t, %1; cvt.u32.u64 %0, t; }"
        : "=r"(a) : "l"(p));
    return a;
}

__device__ __forceinline__ void cp_async16(uint32_t dst, const void* src) {
    asm volatile("cp.async.cg.shared.global [%0], [%1], 16;"
                 :: "r"(dst), "l"(src) : "memory");
}

__device__ __forceinline__ void split2(float a, float b, uint32_t& hi, uint32_t& lo) {
    __nv_bfloat162 h = __floats2bfloat162_rn(a, b);
    float ra = a - __low2float(h);
    float rb = b - __high2float(h);
    __nv_bfloat162 l = __floats2bfloat162_rn(ra, rb);
    hi = *(uint32_t*)&h;
    lo = *(uint32_t*)&l;
}

// ---------------------------------------------------------------------------
// Kernel 0: W -> W^T bf16 hi/lo
// ---------------------------------------------------------------------------
__global__ __launch_bounds__(256) void convert_w_kernel(
    const float* __restrict__ Wq, const float* __restrict__ Wk,
    const float* __restrict__ Wv)
{
    int t = blockIdx.x * 256 + threadIdx.x;
    int o = t / (NE_ * HD_);
    int rem = t - o * (NE_ * HD_);
    int k = rem / HD_;
    int n = rem - k * HD_;
    const float* W = (o == 0) ? Wq : (o == 1) ? Wk : Wv;
    float v = W[(size_t)k * HD_ + n];
    __nv_bfloat16 h = __float2bfloat16(v);
    float lo = v - __bfloat162float(h);
    size_t dst = ((size_t)o * HD_ + n) * NE_ + k;
    g_wt_hi[dst] = h;
    g_wt_lo[dst] = __float2bfloat16(lo);
}

// ---------------------------------------------------------------------------
// Kernel 1: fused QKV projection, 512 threads (16 warps: 4m x 4n).
// grid (2, 128): bx = 64-col half of each output, by = 128-row M tile.
// Warp slab = 32 rows x 48 cols of the 192-col (3 outputs x 64) slab.
// ---------------------------------------------------------------------------
#define QSA 40
#define QAF_B 0
#define QAH_B 18432
#define QAL_B 28672
#define QB_B  38912
#define QSTG_B 69632
#define QKV_SMEM_B (2 * QSTG_B)

__device__ __forceinline__ void qkv_issue(const float* __restrict__ x,
                                          int bx, int m0, int k0,
                                          uint32_t sb_st, int tid)
{
#pragma unroll
    for (int i = 0; i < 2; i++) {            // A fp32: 1024 x 16B
        int c = tid + i * 512;
        int r = c >> 3, q = c & 7;
        cp_async16(sb_st + QAF_B + (uint32_t)(r * 144 + q * 16),
                   x + (size_t)(m0 + r) * NE_ + k0 + q * 4);
    }
#pragma unroll
    for (int i = 0; i < 3; i++) {            // B: 6 tiles x 256 x 16B
        int c = tid + i * 512;
        int tl = c >> 8, idx = c & 255;
        int r = idx >> 2, q = idx & 3;
        int o = tl >> 1, wh = tl & 1;
        const __nv_bfloat16* src = (wh ? g_wt_lo : g_wt_hi)
            + (size_t)(o * HD_ + bx * 64 + r) * NE_ + k0 + q * 8;
        cp_async16(sb_st + QB_B + (uint32_t)(tl * 5120 + r * 80 + q * 16), src);
    }
    asm volatile("cp.async.commit_group;" ::: "memory");
}

__global__ __launch_bounds__(512, 1) void qkv_hmma_kernel(const float* __restrict__ x)
{
    extern __shared__ char qsm[];
    const uint32_t sbu = smem_u32(qsm);
    const int bx = blockIdx.x;
    const int m0 = blockIdx.y * 128;
    const int tid = threadIdx.x;
    const int wid = tid >> 5, lane = tid & 31;
    const int wm = wid & 3, wn = wid >> 2;
    const int g = lane >> 2, t = lane & 3;

    const uint32_t b40 = (uint32_t)(((((lane >> 4) & 1) << 3) + (lane & 7)) * QSA
                                    + (((lane >> 3) & 1) << 3));
    const uint32_t a40 = (uint32_t)(((((lane >> 3) & 1) << 3) + (lane & 7)) * QSA
                                    + (((lane >> 4) & 1) << 3));

    float acc[2][6][4];
#pragma unroll
    for (int mt = 0; mt < 2; mt++)
#pragma unroll
        for (int nt = 0; nt < 6; nt++)
#pragma unroll
            for (int c = 0; c < 4; c++) acc[mt][nt][c] = 0.f;

    qkv_issue(x, bx, m0, 0, sbu, tid);

#pragma unroll 1
    for (int kb = 0; kb < NE_ / 32; kb++) {
        const int st = kb & 1;
        const uint32_t sb_st = sbu + st * QSTG_B;
        if (kb < NE_ / 32 - 1) {
            qkv_issue(x, bx, m0, (kb + 1) * 32, sbu + (st ^ 1) * QSTG_B, tid);
            asm volatile("cp.async.wait_group 1;" ::: "memory");
        } else {
            asm volatile("cp.async.wait_group 0;" ::: "memory");
        }
        __syncthreads();

        // convert AF fp32 -> AH/AL bf16 (2048 pairs, 512 threads x 4)
#pragma unroll
        for (int i = 0; i < 4; i++) {
            int pidx = tid + i * 512;
            int r = pidx >> 4, pc = (pidx & 15) * 2;
            float2 v = *(const float2*)(qsm + st * QSTG_B + QAF_B + r * 144 + pc * 4);
            uint32_t h, l;
            split2(v.x, v.y, h, l);
            *(uint32_t*)(qsm + st * QSTG_B + QAH_B + r * 80 + pc * 2) = h;
            *(uint32_t*)(qsm + st * QSTG_B + QAL_B + r * 80 + pc * 2) = l;
        }
        __syncthreads();

#pragma unroll
        for (int ks = 0; ks < 2; ks++) {
            uint32_t a[2][4];
#pragma unroll
            for (int mt = 0; mt < 2; mt++)
                ldsm_x4(a[mt][0], a[mt][1], a[mt][2], a[mt][3],
                        sb_st + QAH_B
                        + 2 * (uint32_t)((wm * 32 + mt * 16) * QSA + ks * 16 + a40));
#pragma unroll
            for (int wh = 0; wh < 2; wh++) {
#pragma unroll
                for (int n2 = 0; n2 < 3; n2++) {
                    int col = wn * 48 + n2 * 16;
                    int o = col >> 6, rn = col & 63;
                    uint32_t b0, b1, b2, b3;
                    ldsm_x4(b0, b1, b2, b3,
                            sb_st + QB_B + (uint32_t)((o * 2 + wh) * 5120)
                            + 2 * (uint32_t)(rn * QSA + ks * 16 + b40));
                    hmma16816(acc[0][n2 * 2],     a[0], b0, b1);
                    hmma16816(acc[1][n2 * 2],     a[1], b0, b1);
                    hmma16816(acc[0][n2 * 2 + 1], a[0], b2, b3);
                    hmma16816(acc[1][n2 * 2 + 1], a[1], b2, b3);
                }
            }
#pragma unroll
            for (int mt = 0; mt < 2; mt++)
                ldsm_x4(a[mt][0], a[mt][1], a[mt][2], a[mt][3],
                        sb_st + QAL_B
                        + 2 * (uint32_t)((wm * 32 + mt * 16) * QSA + ks * 16 + a40));
#pragma unroll
            for (int n2 = 0; n2 < 3; n2++) {
                int col = wn * 48 + n2 * 16;
                int o = col >> 6, rn = col & 63;
                uint32_t b0, b1, b2, b3;
                ldsm_x4(b0, b1, b2, b3,
                        sb_st + QB_B + (uint32_t)(o * 2 * 5120)
                        + 2 * (uint32_t)(rn * QSA + ks * 16 + b40));
                hmma16816(acc[0][n2 * 2],     a[0], b0, b1);
                hmma16816(acc[1][n2 * 2],     a[1], b0, b1);
                hmma16816(acc[0][n2 * 2 + 1], a[0], b2, b3);
                hmma16816(acc[1][n2 * 2 + 1], a[1], b2, b3);
            }
        }
        __syncthreads();
    }

    // ---- epilogue: Q/K direct hi/lo; V via smem transpose ----
    const int bidx = m0 >> 12;
    const int tok0 = m0 & (T_ - 1);
    float* sT = (float*)qsm;      // [64 hd][132 rows] fp32
#pragma unroll
    for (int mt = 0; mt < 2; mt++) {
#pragma unroll
        for (int nt = 0; nt < 6; nt++) {
            int col192 = wn * 48 + nt * 8;
            int o = col192 >> 6, c64 = col192 & 63;
            if (o < 2) {
                __nv_bfloat16* Hh = o ? g_Khi : g_Qhi;
                __nv_bfloat16* Hl = o ? g_Klo : g_Qlo;
                float sc = o ? 1.0f : 0.08838834764831845f;
                int row = m0 + wm * 32 + mt * 16 + g;
                int colg = bx * 64 + c64 + t * 2;
                uint32_t h0, l0, h1, l1;
                split2(acc[mt][nt][0] * sc, acc[mt][nt][1] * sc, h0, l0);
                split2(acc[mt][nt][2] * sc, acc[mt][nt][3] * sc, h1, l1);
                *(uint32_t*)&Hh[(size_t)row * HD_ + colg] = h0;
                *(uint32_t*)&Hl[(size_t)row * HD_ + colg] = l0;
                *(uint32_t*)&Hh[(size_t)(row + 8) * HD_ + colg] = h1;
                *(uint32_t*)&Hl[(size_t)(row + 8) * HD_ + colg] = l1;
            } else {
                int row = wm * 32 + mt * 16 + g;
                int col = c64 + t * 2;
                sT[(col)     * 132 + row]     = acc[mt][nt][0];
                sT[(col + 1) * 132 + row]     = acc[mt][nt][1];
                sT[(col)     * 132 + row + 8] = acc[mt][nt][2];
                sT[(col + 1) * 132 + row + 8] = acc[mt][nt][3];
            }
        }
    }
    __syncthreads();
#pragma unroll
    for (int i = 0; i < 2; i++) {
        int c = tid + i * 512;
        int hd = c >> 4, tk = (c & 15) * 8;
        const float* sr = sT + hd * 132 + tk;
        uint32_t h[4], l[4];
#pragma unroll
        for (int q = 0; q < 4; q++) split2(sr[2 * q], sr[2 * q + 1], h[q], l[q]);
        size_t base = ((size_t)bidx * HD_ + bx * 64 + hd) * T_ + tok0 + tk;
        *(uint4*)(g_Vthi + base) = make_uint4(h[0], h[1], h[2], h[3]);
        *(uint4*)(g_Vtlo + base) = make_uint4(l[0], l[1], l[2], l[3]);
    }
}

// ---------------------------------------------------------------------------
// Kernel 2: causal flash attention, 512 threads (16 warps: 4m x 4n).
// Warp: S slab 16 rows x 16 cols; O slab 16 rows x 32 cols. Sequential fold.
// ---------------------------------------------------------------------------
#define SAK 136
#define SAV 72
#define SAP 72
#define AQ_HI 0
#define AQ_LO 8704
#define A_PH  17408
#define A_PL  22016
#define A_MRED 26624                     // 4x64 floats = 512 halves
#define A_LRED 27136                     // 4x64 floats
#define A_KOFF 27648
#define A_KSTG 17408
#define A_VOFF (A_KOFF + 2 * A_KSTG)
#define A_VHALF 9216
#define A_VSTG (2 * A_VHALF)
#define A_END (A_VOFF + 2 * A_VSTG)
#define ATTN_SMEM_B (A_END * 2)

__device__ __forceinline__ void load_kv_tile(int b, int kt, int st, int tid,
                                             uint32_t sbu)
{
#pragma unroll
    for (int i = 0; i < 4; i++) {
        int c = tid + i * 512;
        int arr = c >> 10, idx = c & 1023;
        int r = idx >> 4, ch = (idx & 15) * 8;
        const __nv_bfloat16* src = (arr ? g_Klo : g_Khi)
            + ((size_t)(b * T_ + kt * 64 + r)) * HD_ + ch;
        uint32_t dst = sbu + (uint32_t)(A_KOFF + st * A_KSTG + arr * (64 * SAK)
                                        + r * SAK + ch) * 2;
        cp_async16(dst, src);
    }
#pragma unroll
    for (int i = 0; i < 4; i++) {
        int c = tid + i * 512;
        int arr = c >> 10, idx = c & 1023;
        int hd = idx >> 3, ch = (idx & 7) * 8;
        const __nv_bfloat16* src = (arr ? g_Vtlo : g_Vthi)
            + ((size_t)b * HD_ + hd) * T_ + kt * 64 + ch;
        uint32_t dst = sbu + (uint32_t)(A_VOFF + st * A_VSTG + arr * A_VHALF
                                        + hd * SAV + ch) * 2;
        cp_async16(dst, src);
    }
    asm volatile("cp.async.commit_group;" ::: "memory");
}

__global__ __launch_bounds__(512, 1) void attn_hmma_kernel(float* __restrict__ out)
{
    extern __shared__ __nv_bfloat16 sb[];
    const uint32_t sbu = smem_u32(sb);
    const int b   = blockIdx.y;
    const int p   = blockIdx.x;
    const int tid = threadIdx.x;
    const int wid = tid >> 5, lane = tid & 31;
    const int g   = lane >> 2, t = lane & 3;
    const int wm  = wid & 3, wn = wid >> 2;     // 4 m-warps x 4 n-warps
    float* mred = (float*)(sb + A_MRED);
    float* lred = (float*)(sb + A_LRED);

    const uint32_t aK = (uint32_t)(((((lane >> 3) & 1) << 3) + (lane & 7)) * SAK
                                   + (((lane >> 4) & 1) << 3));
    const uint32_t bK = (uint32_t)(((((lane >> 4) & 1) << 3) + (lane & 7)) * SAK
                                   + (((lane >> 3) & 1) << 3));
    const uint32_t aP = (uint32_t)(((((lane >> 3) & 1) << 3) + (lane & 7)) * SAP
                                   + (((lane >> 4) & 1) << 3));
    const uint32_t bV = (uint32_t)(((((lane >> 4) & 1) << 3) + (lane & 7)) * SAV
                                   + (((lane >> 3) & 1) << 3));

    int stg = 0;

#pragma unroll 1
    for (int ph = 0; ph < 2; ph++) {
        const int qt = ph ? (63 - p) : p;
        const int q0 = qt * 64;
        const int n  = qt + 1;

#pragma unroll
        for (int i = 0; i < 4; i++) {
            int c = tid + i * 512;
            int arr = c >> 10, idx = c & 1023;
            int r = idx >> 4, c8 = (idx & 15) * 8;
            const __nv_bfloat16* src = (arr ? g_Qlo : g_Qhi)
                + ((size_t)(b * T_ + q0 + r)) * HD_ + c8;
            *(uint4*)&sb[(arr ? AQ_LO : AQ_HI) + r * SAK + c8] = *(const uint4*)src;
        }
        load_kv_tile(b, 0, stg, tid, sbu);
        int cur = stg; stg ^= 1;
        __syncthreads();

        float m0r = -INFINITY, m1r = -INFINITY, l0r = 0.f, l1r = 0.f;
        float oacc[4][4];
#pragma unroll
        for (int nf = 0; nf < 4; nf++)
#pragma unroll
            for (int c = 0; c < 4; c++) oacc[nf][c] = 0.f;

        const int row0 = wm * 16 + g;

#pragma unroll 1
        for (int kt = 0; kt < n; kt++) {
            if (kt + 1 < n) {
                load_kv_tile(b, kt + 1, stg, tid, sbu);
                stg ^= 1;
                asm volatile("cp.async.wait_group 1;" ::: "memory");
            } else {
                asm volatile("cp.async.wait_group 0;" ::: "memory");
            }
            __syncthreads();                                   // sync1

            const uint32_t KhO = (uint32_t)(A_KOFF + cur * A_KSTG);

            float sacc[2][4];
#pragma unroll
            for (int nf = 0; nf < 2; nf++)
#pragma unroll
                for (int c = 0; c < 4; c++) sacc[nf][c] = 0.f;

            // S: Qhi*(Khi,Klo) with shared a-frag, then Qlo*Khi
#pragma unroll
            for (int ks = 0; ks < 8; ks++) {
                uint32_t a[4];
                ldsm_x4(a[0], a[1], a[2], a[3],
                        sbu + 2 * (uint32_t)(AQ_HI + wm * 16 * SAK + ks * 16 + aK));
#pragma unroll
                for (int pp = 0; pp < 2; pp++) {
                    uint32_t b0, b1, b2, b3;
                    ldsm_x4(b0, b1, b2, b3,
                            sbu + 2 * (KhO + (uint32_t)(pp * 64 * SAK)
                                       + (uint32_t)(wn * 16 * SAK + ks * 16) + bK));
                    hmma16816(sacc[0], a, b0, b1);
                    hmma16816(sacc[1], a, b2, b3);
                }
            }
#pragma unroll
            for (int ks = 0; ks < 8; ks++) {
                uint32_t a[4];
                ldsm_x4(a[0], a[1], a[2], a[3],
                        sbu + 2 * (uint32_t)(AQ_LO + wm * 16 * SAK + ks * 16 + aK));
                uint32_t b0, b1, b2, b3;
                ldsm_x4(b0, b1, b2, b3,
                        sbu + 2 * (KhO + (uint32_t)(wn * 16 * SAK + ks * 16) + bK));
                hmma16816(sacc[0], a, b0, b1);
                hmma16816(sacc[1], a, b2, b3);
            }

            if (kt == qt) {
                const int gr = q0 + row0;
#pragma unroll
                for (int nf = 0; nf < 2; nf++) {
                    int col = kt * 64 + wn * 16 + nf * 8 + t * 2;
                    if (col     > gr)     sacc[nf][0] = -INFINITY;
                    if (col + 1 > gr)     sacc[nf][1] = -INFINITY;
                    if (col     > gr + 8) sacc[nf][2] = -INFINITY;
                    if (col + 1 > gr + 8) sacc[nf][3] = -INFINITY;
                }
            }

            float mx0 = fmaxf(sacc[0][0], fmaxf(sacc[0][1],
                              fmaxf(sacc[1][0], sacc[1][1])));
            float mx1 = fmaxf(sacc[0][2], fmaxf(sacc[0][3],
                              fmaxf(sacc[1][2], sacc[1][3])));
            mx0 = fmaxf(mx0, __shfl_xor_sync(0xffffffffu, mx0, 1));
            mx0 = fmaxf(mx0, __shfl_xor_sync(0xffffffffu, mx0, 2));
            mx1 = fmaxf(mx1, __shfl_xor_sync(0xffffffffu, mx1, 1));
            mx1 = fmaxf(mx1, __shfl_xor_sync(0xffffffffu, mx1, 2));
            if (t == 0) {
                mred[wn * 64 + row0]     = mx0;
                mred[wn * 64 + row0 + 8] = mx1;
            }
            __syncthreads();                                   // sync2
            float mn0 = m0r, mn1 = m1r;
#pragma unroll
            for (int w = 0; w < 4; w++) {
                mn0 = fmaxf(mn0, mred[w * 64 + row0]);
                mn1 = fmaxf(mn1, mred[w * 64 + row0 + 8]);
            }
            float al0 = __expf(m0r - mn0), al1 = __expf(m1r - mn1);
            m0r = mn0; m1r = mn1;

            float s0 = 0.f, s1 = 0.f;
#pragma unroll
            for (int nf = 0; nf < 2; nf++) {
                float p00 = __expf(sacc[nf][0] - mn0);
                float p01 = __expf(sacc[nf][1] - mn0);
                float p10 = __expf(sacc[nf][2] - mn1);
                float p11 = __expf(sacc[nf][3] - mn1);
                s0 += p00 + p01;
                s1 += p10 + p11;
                uint32_t h0, l0, h1, l1;
                split2(p00, p01, h0, l0);
                split2(p10, p11, h1, l1);
                int colh = wn * 16 + nf * 8 + t * 2;
                *(uint32_t*)&sb[A_PH + (row0)     * SAP + colh] = h0;
                *(uint32_t*)&sb[A_PL + (row0)     * SAP + colh] = l0;
                *(uint32_t*)&sb[A_PH + (row0 + 8) * SAP + colh] = h1;
                *(uint32_t*)&sb[A_PL + (row0 + 8) * SAP + colh] = l1;
            }
            s0 += __shfl_xor_sync(0xffffffffu, s0, 1);
            s0 += __shfl_xor_sync(0xffffffffu, s0, 2);
            s1 += __shfl_xor_sync(0xffffffffu, s1, 1);
            s1 += __shfl_xor_sync(0xffffffffu, s1, 2);
            if (t == 0) {
                lred[wn * 64 + row0]     = s0;
                lred[wn * 64 + row0 + 8] = s1;
            }
            __syncthreads();                                   // sync3
            float sg0 = 0.f, sg1 = 0.f;
#pragma unroll
            for (int w = 0; w < 4; w++) {
                sg0 += lred[w * 64 + row0];
                sg1 += lred[w * 64 + row0 + 8];
            }
            l0r = l0r * al0 + sg0;
            l1r = l1r * al1 + sg1;

#pragma unroll
            for (int nf = 0; nf < 4; nf++) {
                oacc[nf][0] *= al0; oacc[nf][1] *= al0;
                oacc[nf][2] *= al1; oacc[nf][3] *= al1;
            }

#pragma unroll
            for (int pass = 0; pass < 3; pass++) {
                const uint32_t ApO = (pass == 2) ? (uint32_t)A_PL : (uint32_t)A_PH;
                const uint32_t VpO = (uint32_t)(A_VOFF + cur * A_VSTG
                                                + ((pass == 1) ? A_VHALF : 0));
#pragma unroll
                for (int kk = 0; kk < 4; kk++) {
                    uint32_t a[4];
                    ldsm_x4(a[0], a[1], a[2], a[3],
                            sbu + 2 * (ApO + (uint32_t)(wm * 16 * SAP + kk * 16) + aP));
#pragma unroll
                    for (int n2 = 0; n2 < 2; n2++) {
                        uint32_t b0, b1, b2, b3;
                        ldsm_x4(b0, b1, b2, b3,
                                sbu + 2 * (VpO + (uint32_t)((wn * 32 + n2 * 16) * SAV
                                                            + kk * 16) + bV));
                        hmma16816(oacc[n2 * 2],     a, b0, b1);
                        hmma16816(oacc[n2 * 2 + 1], a, b2, b3);
                    }
                }
            }
            cur ^= (kt + 1 < n) ? 1 : 0;
            __syncthreads();                                   // sync4
        }

        const float i0 = 1.0f / l0r, i1 = 1.0f / l1r;
        const int grow = b * T_ + q0 + row0;
#pragma unroll
        for (int nf = 0; nf < 4; nf++) {
            int col = wn * 32 + nf * 8 + t * 2;
            *(float2*)&out[(size_t)grow * HD_ + col] =
                make_float2(oacc[nf][0] * i0, oacc[nf][1] * i0);
            *(float2*)&out[(size_t)(grow + 8) * HD_ + col] =
                make_float2(oacc[nf][2] * i1, oacc[nf][3] * i1);
        }
    }
}

// ---------------------------------------------------------------------------
extern "C" void kernel_launch(void* const* d_in, const int* in_sizes, int n_in,
                              void* d_out, int out_size)
{
    const float* x  = (const float*)d_in[0];
    const float* Wq = (const float*)d_in[1];
    const float* Wk = (const float*)d_in[2];
    const float* Wv = (const float*)d_in[3];
    float* out = (float*)d_out;
    (void)in_sizes; (void)n_in; (void)out_size;

    cudaFuncSetAttribute(qkv_hmma_kernel,
                         cudaFuncAttributeMaxDynamicSharedMemorySize, QKV_SMEM_B);
    cudaFuncSetAttribute(attn_hmma_kernel,
                         cudaFuncAttributeMaxDynamicSharedMemorySize, ATTN_SMEM_B);

    convert_w_kernel<<<(3 * NE_ * HD_) / 256, 256>>>(Wq, Wk, Wv);
    qkv_hmma_kernel<<<dim3(2, 128), 512, QKV_SMEM_B>>>(x);
    attn_hmma_kernel<<<dim3(32, B_), 512, ATTN_SMEM_B>>>(out);
}

// round 16
// speedup vs baseline: 1.0443x; 1.0443x over previous
#include <cuda_runtime.h>
#include <cuda_bf16.h>
#include <math.h>
#include <stdint.h>

#define B_  4
#define T_  4096
#define NE_ 2048
#define HD_ 128
#define M_TOT (B_ * T_)

// ---------------------------------------------------------------------------
// Device scratch (no allocations allowed)
// ---------------------------------------------------------------------------
__device__ __nv_bfloat16 g_wt_hi[3 * HD_ * NE_];
__device__ __nv_bfloat16 g_wt_lo[3 * HD_ * NE_];
__device__ __nv_bfloat16 g_Qhi[M_TOT * HD_], g_Qlo[M_TOT * HD_];
__device__ __nv_bfloat16 g_Khi[M_TOT * HD_], g_Klo[M_TOT * HD_];
__device__ __nv_bfloat16 g_Vthi[M_TOT * HD_], g_Vtlo[M_TOT * HD_];

// ---------------------------------------------------------------------------
// helpers
// ---------------------------------------------------------------------------
__device__ __forceinline__ void hmma16816(float* c, const uint32_t* a,
                                          uint32_t b0, uint32_t b1)
{
    asm volatile(
        "mma.sync.aligned.m16n8k16.row.col.f32.bf16.bf16.f32 "
        "{%0,%1,%2,%3}, {%4,%5,%6,%7}, {%8,%9}, {%0,%1,%2,%3};"
        : "+f"(c[0]), "+f"(c[1]), "+f"(c[2]), "+f"(c[3])
        : "r"(a[0]), "r"(a[1]), "r"(a[2]), "r"(a[3]), "r"(b0), "r"(b1));
}

__device__ __forceinline__ void ldsm_x4(uint32_t& r0, uint32_t& r1,
                                        uint32_t& r2, uint32_t& r3, uint32_t addr)
{
    asm volatile("ldmatrix.sync.aligned.m8n8.x4.shared.b16 {%0,%1,%2,%3}, [%4];"
                 : "=r"(r0), "=r"(r1), "=r"(r2), "=r"(r3) : "r"(addr));
}

__device__ __forceinline__ uint32_t smem_u32(const void* p) {
    uint32_t a;
    asm("{ .reg .u64 t; cvta.to.shared.u64 t, %1; cvt.u32.u64 %0, t; }"
        : "=r"(a) : "l"(p));
    return a;
}

__device__ __forceinline__ void cp_async16(uint32_t dst, const void* src) {
    asm volatile("cp.async.cg.shared.global [%0], [%1], 16;"
                 :: "r"(dst), "l"(src) : "memory");
}

__device__ __forceinline__ void split2(float a, float b, uint32_t& hi, uint32_t& lo) {
    __nv_bfloat162 h = __floats2bfloat162_rn(a, b);
    float ra = a - __low2float(h);
    float rb = b - __high2float(h);
    __nv_bfloat162 l = __floats2bfloat162_rn(ra, rb);
    hi = *(uint32_t*)&h;
    lo = *(uint32_t*)&l;
}

// ---------------------------------------------------------------------------
// Kernel 0: W -> W^T bf16 hi/lo
// ---------------------------------------------------------------------------
__global__ __launch_bounds__(256) void convert_w_kernel(
    const float* __restrict__ Wq, const float* __restrict__ Wk,
    const float* __restrict__ Wv)
{
    int t = blockIdx.x * 256 + threadIdx.x;
    int o = t / (NE_ * HD_);
    int rem = t - o * (NE_ * HD_);
    int k = rem / HD_;
    int n = rem - k * HD_;
    const float* W = (o == 0) ? Wq : (o == 1) ? Wk : Wv;
    float v = W[(size_t)k * HD_ + n];
    __nv_bfloat16 h = __float2bfloat16(v);
    float lo = v - __bfloat162float(h);
    size_t dst = ((size_t)o * HD_ + n) * NE_ + k;
    g_wt_hi[dst] = h;
    g_wt_lo[dst] = __float2bfloat16(lo);
}

// ---------------------------------------------------------------------------
// Kernel 1: fused QKV projection, 256 thr (8 warps: 4m x 2n), grid (2, 128).
// Merged-pass inner loop: each b-frag load feeds both hi and lo a-products.
// ---------------------------------------------------------------------------
#define QSA 40
#define QAF_B 0
#define QAH_B 18432
#define QAL_B 28672
#define QB_B  38912
#define QSTG_B 69632
#define QKV_SMEM_B (2 * QSTG_B)

__device__ __forceinline__ void qkv_issue(const float* __restrict__ x,
                                          int bx, int m0, int k0,
                                          uint32_t sb_st, int tid)
{
#pragma unroll
    for (int i = 0; i < 4; i++) {            // A fp32: 1024 x 16B
        int c = tid + i * 256;
        int r = c >> 3, q = c & 7;
        cp_async16(sb_st + QAF_B + (uint32_t)(r * 144 + q * 16),
                   x + (size_t)(m0 + r) * NE_ + k0 + q * 4);
    }
#pragma unroll
    for (int i = 0; i < 6; i++) {            // B: 6 tiles x 256 x 16B
        int c = tid + i * 256;
        int tl = c >> 8, idx = c & 255;
        int r = idx >> 2, q = idx & 3;
        int o = tl >> 1, wh = tl & 1;
        const __nv_bfloat16* src = (wh ? g_wt_lo : g_wt_hi)
            + (size_t)(o * HD_ + bx * 64 + r) * NE_ + k0 + q * 8;
        cp_async16(sb_st + QB_B + (uint32_t)(tl * 5120 + r * 80 + q * 16), src);
    }
    asm volatile("cp.async.commit_group;" ::: "memory");
}

__global__ __launch_bounds__(256) void qkv_hmma_kernel(const float* __restrict__ x)
{
    extern __shared__ char qsm[];
    const uint32_t sbu = smem_u32(qsm);
    const int bx = blockIdx.x;
    const int m0 = blockIdx.y * 128;
    const int tid = threadIdx.x;
    const int wid = tid >> 5, lane = tid & 31;
    const int wm = wid >> 1, wn = wid & 1;
    const int g = lane >> 2, t = lane & 3;

    const uint32_t b40 = (uint32_t)(((((lane >> 4) & 1) << 3) + (lane & 7)) * QSA
                                    + (((lane >> 3) & 1) << 3));
    const uint32_t a40 = (uint32_t)(((((lane >> 3) & 1) << 3) + (lane & 7)) * QSA
                                    + (((lane >> 4) & 1) << 3));

    float acc[2][12][4];
#pragma unroll
    for (int mt = 0; mt < 2; mt++)
#pragma unroll
        for (int nt = 0; nt < 12; nt++)
#pragma unroll
            for (int c = 0; c < 4; c++) acc[mt][nt][c] = 0.f;

    qkv_issue(x, bx, m0, 0, sbu, tid);

#pragma unroll 1
    for (int kb = 0; kb < NE_ / 32; kb++) {
        const int st = kb & 1;
        const uint32_t sb_st = sbu + st * QSTG_B;
        if (kb < NE_ / 32 - 1) {
            qkv_issue(x, bx, m0, (kb + 1) * 32, sbu + (st ^ 1) * QSTG_B, tid);
            asm volatile("cp.async.wait_group 1;" ::: "memory");
        } else {
            asm volatile("cp.async.wait_group 0;" ::: "memory");
        }
        __syncthreads();

        // convert AF fp32 -> AH/AL bf16 (2048 pairs)
#pragma unroll
        for (int i = 0; i < 8; i++) {
            int pidx = tid + i * 256;
            int r = pidx >> 4, pc = (pidx & 15) * 2;
            float2 v = *(const float2*)(qsm + st * QSTG_B + QAF_B + r * 144 + pc * 4);
            uint32_t h, l;
            split2(v.x, v.y, h, l);
            *(uint32_t*)(qsm + st * QSTG_B + QAH_B + r * 80 + pc * 2) = h;
            *(uint32_t*)(qsm + st * QSTG_B + QAL_B + r * 80 + pc * 2) = l;
        }
        __syncthreads();

#pragma unroll
        for (int ks = 0; ks < 2; ks++) {
            uint32_t ah[2][4], al[2][4];
#pragma unroll
            for (int mt = 0; mt < 2; mt++) {
                ldsm_x4(ah[mt][0], ah[mt][1], ah[mt][2], ah[mt][3],
                        sb_st + QAH_B
                        + 2 * (uint32_t)((wm * 32 + mt * 16) * QSA + ks * 16 + a40));
                ldsm_x4(al[mt][0], al[mt][1], al[mt][2], al[mt][3],
                        sb_st + QAL_B
                        + 2 * (uint32_t)((wm * 32 + mt * 16) * QSA + ks * 16 + a40));
            }
#pragma unroll
            for (int n2 = 0; n2 < 6; n2++) {
                int col = wn * 96 + n2 * 16;
                int o = col >> 6, rn = col & 63;
                uint32_t b0, b1, b2, b3;
                // b_hi: feeds Ahi*Bhi and Alo*Bhi
                ldsm_x4(b0, b1, b2, b3,
                        sb_st + QB_B + (uint32_t)(o * 2 * 5120)
                        + 2 * (uint32_t)(rn * QSA + ks * 16 + b40));
                hmma16816(acc[0][n2 * 2],     ah[0], b0, b1);
                hmma16816(acc[1][n2 * 2],     ah[1], b0, b1);
                hmma16816(acc[0][n2 * 2 + 1], ah[0], b2, b3);
                hmma16816(acc[1][n2 * 2 + 1], ah[1], b2, b3);
                hmma16816(acc[0][n2 * 2],     al[0], b0, b1);
                hmma16816(acc[1][n2 * 2],     al[1], b0, b1);
                hmma16816(acc[0][n2 * 2 + 1], al[0], b2, b3);
                hmma16816(acc[1][n2 * 2 + 1], al[1], b2, b3);
                // b_lo: feeds Ahi*Blo
                ldsm_x4(b0, b1, b2, b3,
                        sb_st + QB_B + (uint32_t)((o * 2 + 1) * 5120)
                        + 2 * (uint32_t)(rn * QSA + ks * 16 + b40));
                hmma16816(acc[0][n2 * 2],     ah[0], b0, b1);
                hmma16816(acc[1][n2 * 2],     ah[1], b0, b1);
                hmma16816(acc[0][n2 * 2 + 1], ah[0], b2, b3);
                hmma16816(acc[1][n2 * 2 + 1], ah[1], b2, b3);
            }
        }
        __syncthreads();
    }

    // ---- epilogue: Q/K direct hi/lo; V via smem transpose ----
    const int bidx = m0 >> 12;
    const int tok0 = m0 & (T_ - 1);
#pragma unroll
    for (int mt = 0; mt < 2; mt++) {
#pragma unroll
        for (int nt = 0; nt < 12; nt++) {
            int col192 = wn * 96 + nt * 8;
            int o = col192 >> 6, c64 = col192 & 63;
            if (o < 2) {
                __nv_bfloat16* Hh = o ? g_Khi : g_Qhi;
                __nv_bfloat16* Hl = o ? g_Klo : g_Qlo;
                float sc = o ? 1.0f : 0.08838834764831845f;
                int row = m0 + wm * 32 + mt * 16 + g;
                int colg = bx * 64 + c64 + t * 2;
                uint32_t h0, l0, h1, l1;
                split2(acc[mt][nt][0] * sc, acc[mt][nt][1] * sc, h0, l0);
                split2(acc[mt][nt][2] * sc, acc[mt][nt][3] * sc, h1, l1);
                *(uint32_t*)&Hh[(size_t)row * HD_ + colg] = h0;
                *(uint32_t*)&Hl[(size_t)row * HD_ + colg] = l0;
                *(uint32_t*)&Hh[(size_t)(row + 8) * HD_ + colg] = h1;
                *(uint32_t*)&Hl[(size_t)(row + 8) * HD_ + colg] = l1;
            }
        }
    }
    float* sT = (float*)qsm;      // [64 hd][132 rows] fp32
    if (wn == 1) {
#pragma unroll
        for (int mt = 0; mt < 2; mt++) {
            int row = wm * 32 + mt * 16 + g;
#pragma unroll
            for (int nt = 4; nt < 12; nt++) {
                int col = nt * 8 - 32 + t * 2;
                sT[(col)     * 132 + row]     = acc[mt][nt][0];
                sT[(col + 1) * 132 + row]     = acc[mt][nt][1];
                sT[(col)     * 132 + row + 8] = acc[mt][nt][2];
                sT[(col + 1) * 132 + row + 8] = acc[mt][nt][3];
            }
        }
    }
    __syncthreads();
#pragma unroll
    for (int i = 0; i < 4; i++) {
        int c = tid + i * 256;
        int hd = c >> 4, tk = (c & 15) * 8;
        const float* sr = sT + hd * 132 + tk;
        uint32_t h[4], l[4];
#pragma unroll
        for (int q = 0; q < 4; q++) split2(sr[2 * q], sr[2 * q + 1], h[q], l[q]);
        size_t base = ((size_t)bidx * HD_ + bx * 64 + hd) * T_ + tok0 + tk;
        *(uint4*)(g_Vthi + base) = make_uint4(h[0], h[1], h[2], h[3]);
        *(uint4*)(g_Vtlo + base) = make_uint4(l[0], l[1], l[2], l[3]);
    }
}

// ---------------------------------------------------------------------------
// Kernel 2: causal flash attention, 256 thr (4m x 2n), sequential fold,
// merged-pass inner loops (b-frag reuse across hi/lo a-products).
// ---------------------------------------------------------------------------
#define SAK 136
#define SAV 72
#define SAP 72
#define AQ_HI 0
#define AQ_LO 8704
#define A_PH  17408
#define A_PL  22016
#define A_MRED 26624
#define A_LRED 26880
#define A_KOFF 27648
#define A_KSTG 17408
#define A_VOFF (A_KOFF + 2 * A_KSTG)
#define A_VHALF 9216
#define A_VSTG (2 * A_VHALF)
#define A_END (A_VOFF + 2 * A_VSTG)
#define ATTN_SMEM_B (A_END * 2)

__device__ __forceinline__ void load_kv_tile(int b, int kt, int st, int tid,
                                             uint32_t sbu)
{
#pragma unroll
    for (int i = 0; i < 8; i++) {
        int c = tid + i * 256;
        int arr = c >> 10, idx = c & 1023;
        int r = idx >> 4, ch = (idx & 15) * 8;
        const __nv_bfloat16* src = (arr ? g_Klo : g_Khi)
            + ((size_t)(b * T_ + kt * 64 + r)) * HD_ + ch;
        uint32_t dst = sbu + (uint32_t)(A_KOFF + st * A_KSTG + arr * (64 * SAK)
                                        + r * SAK + ch) * 2;
        cp_async16(dst, src);
    }
#pragma unroll
    for (int i = 0; i < 8; i++) {
        int c = tid + i * 256;
        int arr = c >> 10, idx = c & 1023;
        int hd = idx >> 3, ch = (idx & 7) * 8;
        const __nv_bfloat16* src = (arr ? g_Vtlo : g_Vthi)
            + ((size_t)b * HD_ + hd) * T_ + kt * 64 + ch;
        uint32_t dst = sbu + (uint32_t)(A_VOFF + st * A_VSTG + arr * A_VHALF
                                        + hd * SAV + ch) * 2;
        cp_async16(dst, src);
    }
    asm volatile("cp.async.commit_group;" ::: "memory");
}

__global__ __launch_bounds__(256, 1) void attn_hmma_kernel(float* __restrict__ out)
{
    extern __shared__ __nv_bfloat16 sb[];
    const uint32_t sbu = smem_u32(sb);
    const int b   = blockIdx.y;
    const int p   = blockIdx.x;
    const int tid = threadIdx.x;
    const int wid = tid >> 5, lane = tid & 31;
    const int g   = lane >> 2, t = lane & 3;
    const int wm  = wid & 3, wn = wid >> 2;
    float* mred = (float*)(sb + A_MRED);
    float* lred = (float*)(sb + A_LRED);

    const uint32_t aK = (uint32_t)(((((lane >> 3) & 1) << 3) + (lane & 7)) * SAK
                                   + (((lane >> 4) & 1) << 3));
    const uint32_t bK = (uint32_t)(((((lane >> 4) & 1) << 3) + (lane & 7)) * SAK
                                   + (((lane >> 3) & 1) << 3));
    const uint32_t aP = (uint32_t)(((((lane >> 3) & 1) << 3) + (lane & 7)) * SAP
                                   + (((lane >> 4) & 1) << 3));
    const uint32_t bV = (uint32_t)(((((lane >> 4) & 1) << 3) + (lane & 7)) * SAV
                                   + (((lane >> 3) & 1) << 3));

    int stg = 0;

#pragma unroll 1
    for (int ph = 0; ph < 2; ph++) {
        const int qt = ph ? (63 - p) : p;
        const int q0 = qt * 64;
        const int n  = qt + 1;

#pragma unroll
        for (int i = 0; i < 8; i++) {
            int c = tid + i * 256;
            int arr = c >> 10, idx = c & 1023;
            int r = idx >> 4, c8 = (idx & 15) * 8;
            const __nv_bfloat16* src = (arr ? g_Qlo : g_Qhi)
                + ((size_t)(b * T_ + q0 + r)) * HD_ + c8;
            *(uint4*)&sb[(arr ? AQ_LO : AQ_HI) + r * SAK + c8] = *(const uint4*)src;
        }
        load_kv_tile(b, 0, stg, tid, sbu);
        int cur = stg; stg ^= 1;
        __syncthreads();

        float m0r = -INFINITY, m1r = -INFINITY, l0r = 0.f, l1r = 0.f;
        float oacc[8][4];
#pragma unroll
        for (int nf = 0; nf < 8; nf++)
#pragma unroll
            for (int c = 0; c < 4; c++) oacc[nf][c] = 0.f;

        const int row0 = wm * 16 + g;

#pragma unroll 1
        for (int kt = 0; kt < n; kt++) {
            if (kt + 1 < n) {
                load_kv_tile(b, kt + 1, stg, tid, sbu);
                stg ^= 1;
                asm volatile("cp.async.wait_group 1;" ::: "memory");
            } else {
                asm volatile("cp.async.wait_group 0;" ::: "memory");
            }
            __syncthreads();

            const uint32_t KhO = (uint32_t)(A_KOFF + cur * A_KSTG);

            float sacc[4][4];
#pragma unroll
            for (int nf = 0; nf < 4; nf++)
#pragma unroll
                for (int c = 0; c < 4; c++) sacc[nf][c] = 0.f;

            // ---- S merged: per ks load Qhi,Qlo; per n2: Khi feeds both, Klo hi only
#pragma unroll
            for (int ks = 0; ks < 8; ks++) {
                uint32_t ah[4], al[4];
                ldsm_x4(ah[0], ah[1], ah[2], ah[3],
                        sbu + 2 * (uint32_t)(AQ_HI + wm * 16 * SAK + ks * 16 + aK));
                ldsm_x4(al[0], al[1], al[2], al[3],
                        sbu + 2 * (uint32_t)(AQ_LO + wm * 16 * SAK + ks * 16 + aK));
#pragma unroll
                for (int n2 = 0; n2 < 2; n2++) {
                    uint32_t b0, b1, b2, b3;
                    ldsm_x4(b0, b1, b2, b3,
                            sbu + 2 * (KhO + (uint32_t)((wn * 32 + n2 * 16) * SAK
                                                        + ks * 16) + bK));
                    hmma16816(sacc[n2 * 2],     ah, b0, b1);
                    hmma16816(sacc[n2 * 2 + 1], ah, b2, b3);
                    hmma16816(sacc[n2 * 2],     al, b0, b1);
                    hmma16816(sacc[n2 * 2 + 1], al, b2, b3);
                    ldsm_x4(b0, b1, b2, b3,
                            sbu + 2 * (KhO + (uint32_t)(64 * SAK)
                                       + (uint32_t)((wn * 32 + n2 * 16) * SAK
                                                    + ks * 16) + bK));
                    hmma16816(sacc[n2 * 2],     ah, b0, b1);
                    hmma16816(sacc[n2 * 2 + 1], ah, b2, b3);
                }
            }

            if (kt == qt) {
                const int gr = q0 + row0;
#pragma unroll
                for (int nf = 0; nf < 4; nf++) {
                    int col = kt * 64 + wn * 32 + nf * 8 + t * 2;
                    if (col     > gr)     sacc[nf][0] = -INFINITY;
                    if (col + 1 > gr)     sacc[nf][1] = -INFINITY;
                    if (col     > gr + 8) sacc[nf][2] = -INFINITY;
                    if (col + 1 > gr + 8) sacc[nf][3] = -INFINITY;
                }
            }

            float mx0 = -INFINITY, mx1 = -INFINITY;
#pragma unroll
            for (int nf = 0; nf < 4; nf++) {
                mx0 = fmaxf(mx0, fmaxf(sacc[nf][0], sacc[nf][1]));
                mx1 = fmaxf(mx1, fmaxf(sacc[nf][2], sacc[nf][3]));
            }
            mx0 = fmaxf(mx0, __shfl_xor_sync(0xffffffffu, mx0, 1));
            mx0 = fmaxf(mx0, __shfl_xor_sync(0xffffffffu, mx0, 2));
            mx1 = fmaxf(mx1, __shfl_xor_sync(0xffffffffu, mx1, 1));
            mx1 = fmaxf(mx1, __shfl_xor_sync(0xffffffffu, mx1, 2));
            if (t == 0) {
                mred[wn * 64 + row0]     = mx0;
                mred[wn * 64 + row0 + 8] = mx1;
            }
            __syncthreads();
            float mn0 = fmaxf(m0r, fmaxf(mx0, mred[(wn ^ 1) * 64 + row0]));
            float mn1 = fmaxf(m1r, fmaxf(mx1, mred[(wn ^ 1) * 64 + row0 + 8]));
            float al0 = __expf(m0r - mn0), al1 = __expf(m1r - mn1);
            m0r = mn0; m1r = mn1;

            float s0 = 0.f, s1 = 0.f;
#pragma unroll
            for (int nf = 0; nf < 4; nf++) {
                float p00 = __expf(sacc[nf][0] - mn0);
                float p01 = __expf(sacc[nf][1] - mn0);
                float p10 = __expf(sacc[nf][2] - mn1);
                float p11 = __expf(sacc[nf][3] - mn1);
                s0 += p00 + p01;
                s1 += p10 + p11;
                uint32_t h0, l0, h1, l1;
                split2(p00, p01, h0, l0);
                split2(p10, p11, h1, l1);
                int colh = wn * 32 + nf * 8 + t * 2;
                *(uint32_t*)&sb[A_PH + (row0)     * SAP + colh] = h0;
                *(uint32_t*)&sb[A_PL + (row0)     * SAP + colh] = l0;
                *(uint32_t*)&sb[A_PH + (row0 + 8) * SAP + colh] = h1;
                *(uint32_t*)&sb[A_PL + (row0 + 8) * SAP + colh] = l1;
            }
            s0 += __shfl_xor_sync(0xffffffffu, s0, 1);
            s0 += __shfl_xor_sync(0xffffffffu, s0, 2);
            s1 += __shfl_xor_sync(0xffffffffu, s1, 1);
            s1 += __shfl_xor_sync(0xffffffffu, s1, 2);
            if (t == 0) {
                lred[wn * 64 + row0]     = s0;
                lred[wn * 64 + row0 + 8] = s1;
            }
            __syncthreads();
            l0r = l0r * al0 + s0 + lred[(wn ^ 1) * 64 + row0];
            l1r = l1r * al1 + s1 + lred[(wn ^ 1) * 64 + row0 + 8];

#pragma unroll
            for (int nf = 0; nf < 8; nf++) {
                oacc[nf][0] *= al0; oacc[nf][1] *= al0;
                oacc[nf][2] *= al1; oacc[nf][3] *= al1;
            }

            // ---- PV merged: per kk load Ph,Pl; per n2: Vh feeds both, Vl hi only
            const uint32_t VhO = (uint32_t)(A_VOFF + cur * A_VSTG);
#pragma unroll
            for (int kk = 0; kk < 4; kk++) {
                uint32_t ahp[4], alp[4];
                ldsm_x4(ahp[0], ahp[1], ahp[2], ahp[3],
                        sbu + 2 * (uint32_t)(A_PH + wm * 16 * SAP + kk * 16 + aP));
                ldsm_x4(alp[0], alp[1], alp[2], alp[3],
                        sbu + 2 * (uint32_t)(A_PL + wm * 16 * SAP + kk * 16 + aP));
#pragma unroll
                for (int n2 = 0; n2 < 4; n2++) {
                    uint32_t b0, b1, b2, b3;
                    ldsm_x4(b0, b1, b2, b3,
                            sbu + 2 * (VhO + (uint32_t)((wn * 64 + n2 * 16) * SAV
                                                        + kk * 16) + bV));
                    hmma16816(oacc[n2 * 2],     ahp, b0, b1);
                    hmma16816(oacc[n2 * 2 + 1], ahp, b2, b3);
                    hmma16816(oacc[n2 * 2],     alp, b0, b1);
                    hmma16816(oacc[n2 * 2 + 1], alp, b2, b3);
                    ldsm_x4(b0, b1, b2, b3,
                            sbu + 2 * (VhO + (uint32_t)A_VHALF
                                       + (uint32_t)((wn * 64 + n2 * 16) * SAV
                                                    + kk * 16) + bV));
                    hmma16816(oacc[n2 * 2],     ahp, b0, b1);
                    hmma16816(oacc[n2 * 2 + 1], ahp, b2, b3);
                }
            }
            cur ^= (kt + 1 < n) ? 1 : 0;
            __syncthreads();
        }

        const float i0 = 1.0f / l0r, i1 = 1.0f / l1r;
        const int grow = b * T_ + q0 + row0;
#pragma unroll
        for (int nf = 0; nf < 8; nf++) {
            int col = wn * 64 + nf * 8 + t * 2;
            *(float2*)&out[(size_t)grow * HD_ + col] =
                make_float2(oacc[nf][0] * i0, oacc[nf][1] * i0);
            *(float2*)&out[(size_t)(grow + 8) * HD_ + col] =
                make_float2(oacc[nf][2] * i1, oacc[nf][3] * i1);
        }
    }
}

// ---------------------------------------------------------------------------
extern "C" void kernel_launch(void* const* d_in, const int* in_sizes, int n_in,
                              void* d_out, int out_size)
{
    const float* x  = (const float*)d_in[0];
    const float* Wq = (const float*)d_in[1];
    const float* Wk = (const float*)d_in[2];
    const float* Wv = (const float*)d_in[3];
    float* out = (float*)d_out;
    (void)in_sizes; (void)n_in; (void)out_size;

    cudaFuncSetAttribute(qkv_hmma_kernel,
                         cudaFuncAttributeMaxDynamicSharedMemorySize, QKV_SMEM_B);
    cudaFuncSetAttribute(attn_hmma_kernel,
                         cudaFuncAttributeMaxDynamicSharedMemorySize, ATTN_SMEM_B);

    convert_w_kernel<<<(3 * NE_ * HD_) / 256, 256>>>(Wq, Wk, Wv);
    qkv_hmma_kernel<<<dim3(2, 128), 256, QKV_SMEM_B>>>(x);
    attn_hmma_kernel<<<dim3(32, B_), 256, ATTN_SMEM_B>>>(out);
}